// round 1
// baseline (speedup 1.0000x reference)
#include <cuda_runtime.h>
#include <cuda_bf16.h>
#include <math.h>

// Problem constants
#define B_      1
#define S_      2048
#define H_      4096
#define NH_     32
#define NKV_    8
#define HD_     128
#define QKV_O   ((NH_ + 2 * NKV_) * HD_)   // 6144
#define Q_END   (NH_ * HD_)                // 4096
#define K_END   (Q_END + NKV_ * HD_)       // 5120

// Scratch (no allocations allowed)
__device__ float g_qkv[S_ * QKV_O];    // [2048, 6144]
__device__ float g_attn[S_ * H_];      // [2048, 4096]

// ---------------------------------------------------------------------------
// SGEMM: C[M,N] = A[M,K] * B[N,K]^T   (A row-major MxK, B row-major NxK)
// BM=BN=128, BK=16, 256 threads, 8x8 register tile per thread.
// M, N, K all multiples of tile sizes here (no bounds checks).
// ---------------------------------------------------------------------------
__global__ __launch_bounds__(256) void sgemm_nt_kernel(
    const float* __restrict__ A, const float* __restrict__ B,
    float* __restrict__ C, int M, int N, int K)
{
    const int BM = 128, BN = 128, BK = 16;
    __shared__ float As[BK][BM + 4];
    __shared__ float Bs[BK][BN + 4];

    const int tid = threadIdx.x;
    const int m0 = blockIdx.y * BM;
    const int n0 = blockIdx.x * BN;
    const int tr = tid / 16;    // 0..15
    const int tc = tid % 16;    // 0..15

    float acc[8][8];
#pragma unroll
    for (int i = 0; i < 8; i++)
#pragma unroll
        for (int j = 0; j < 8; j++) acc[i][j] = 0.0f;

    for (int k0 = 0; k0 < K; k0 += BK) {
        // Load A tile (128x16) and B tile (128x16), transposed into smem.
#pragma unroll
        for (int it = 0; it < 2; it++) {
            int f = tid + it * 256;          // 0..511 float4 slots
            int row = f >> 2;                // 0..127
            int cv = (f & 3) << 2;           // 0,4,8,12
            float4 a = *(const float4*)&A[(size_t)(m0 + row) * K + k0 + cv];
            As[cv + 0][row] = a.x; As[cv + 1][row] = a.y;
            As[cv + 2][row] = a.z; As[cv + 3][row] = a.w;
            float4 b = *(const float4*)&B[(size_t)(n0 + row) * K + k0 + cv];
            Bs[cv + 0][row] = b.x; Bs[cv + 1][row] = b.y;
            Bs[cv + 2][row] = b.z; Bs[cv + 3][row] = b.w;
        }
        __syncthreads();

#pragma unroll
        for (int k = 0; k < BK; k++) {
            float a[8], b[8];
            float4 a0 = *(const float4*)&As[k][tr * 8];
            float4 a1 = *(const float4*)&As[k][tr * 8 + 4];
            float4 b0 = *(const float4*)&Bs[k][tc * 8];
            float4 b1 = *(const float4*)&Bs[k][tc * 8 + 4];
            a[0]=a0.x; a[1]=a0.y; a[2]=a0.z; a[3]=a0.w;
            a[4]=a1.x; a[5]=a1.y; a[6]=a1.z; a[7]=a1.w;
            b[0]=b0.x; b[1]=b0.y; b[2]=b0.z; b[3]=b0.w;
            b[4]=b1.x; b[5]=b1.y; b[6]=b1.z; b[7]=b1.w;
#pragma unroll
            for (int i = 0; i < 8; i++)
#pragma unroll
                for (int j = 0; j < 8; j++)
                    acc[i][j] = fmaf(a[i], b[j], acc[i][j]);
        }
        __syncthreads();
    }

    // Write back (float4 stores)
#pragma unroll
    for (int i = 0; i < 8; i++) {
        float* crow = &C[(size_t)(m0 + tr * 8 + i) * N + n0 + tc * 8];
        float4 c0 = make_float4(acc[i][0], acc[i][1], acc[i][2], acc[i][3]);
        float4 c1 = make_float4(acc[i][4], acc[i][5], acc[i][6], acc[i][7]);
        *(float4*)&crow[0] = c0;
        *(float4*)&crow[4] = c1;
    }
}

// ---------------------------------------------------------------------------
// RoPE applied in place to q (heads 0..31) and k (heads 32..39) of g_qkv.
// One thread per (s, head, d2) with d2 in [0,64).
// ---------------------------------------------------------------------------
__global__ void rope_kernel(float* __restrict__ qkv)
{
    int idx = blockIdx.x * blockDim.x + threadIdx.x;
    const int total = S_ * (NH_ + NKV_) * (HD_ / 2);   // 2048*40*64
    if (idx >= total) return;
    int d2 = idx & 63;
    int t = idx >> 6;
    int head = t % (NH_ + NKV_);
    int s = t / (NH_ + NKV_);

    // inv_freq = 10000^{-d2/64}; compute in double, then angle in double
    double inv = exp(-((double)(2 * d2) / (double)HD_) * 9.210340371976184);
    double ang = (double)s * inv;
    double sv, cv;
    sincos(ang, &sv, &cv);
    float c = (float)cv, sn = (float)sv;

    size_t base = (size_t)s * QKV_O + head * HD_;   // head<32 -> q, 32..39 -> k
    float x1 = qkv[base + d2];
    float x2 = qkv[base + 64 + d2];
    qkv[base + d2]      = x1 * c - x2 * sn;
    qkv[base + 64 + d2] = x1 * sn + x2 * c;
}

// ---------------------------------------------------------------------------
// Flash attention, fp32, causal, GQA (4 q heads per kv head).
// BQ = BK = 64, D = 128, 256 threads (16x16 grid).
// Per thread: S tile 4x4 (rows tr*4+i, cols tc*4+j),
//             O tile 4x8 (rows tr*4+i, cols tc*8+j).
// Dynamic smem: Qs[64][132] | Kst[128][68] | Vs[64][132] | Ps[64][68]
// ---------------------------------------------------------------------------
#define QS_STRIDE 132
#define KT_STRIDE 68
#define VS_STRIDE 132
#define PS_STRIDE 68
#define SMEM_FLOATS (64*QS_STRIDE + 128*KT_STRIDE + 64*VS_STRIDE + 64*PS_STRIDE)

__global__ __launch_bounds__(256) void flash_attn_kernel(
    const float* __restrict__ qkv, float* __restrict__ attn_out)
{
    extern __shared__ float sm[];
    float* Qs  = sm;                                   // [64][132]
    float* Kst = Qs + 64 * QS_STRIDE;                  // [128][68] (k-major)
    float* Vs  = Kst + 128 * KT_STRIDE;                // [64][132]
    float* Ps  = Vs + 64 * VS_STRIDE;                  // [64][68]

    const int qb   = blockIdx.x;          // 0..31
    const int head = blockIdx.y;          // 0..31
    const int kvh  = head >> 2;           // GQA group
    const int tid  = threadIdx.x;
    const int tr   = tid / 16;            // 0..15
    const int tc   = tid % 16;            // 0..15
    const int q0   = qb * 64;
    const float scale = 0.08838834764831845f;   // 1/sqrt(128)

    // Load Q tile: rows q0..q0+63, cols head*128..+127
#pragma unroll
    for (int it = 0; it < 8; it++) {
        int f = tid + it * 256;          // 0..2047 float4 slots
        int row = f >> 5;                // 0..63
        int cv = (f & 31) << 2;          // 0..124
        float4 v = *(const float4*)&qkv[(size_t)(q0 + row) * QKV_O + head * HD_ + cv];
        float* dst = &Qs[row * QS_STRIDE + cv];
        *(float4*)dst = v;
    }

    float O[4][8];
    float m_i[4], l_i[4];
#pragma unroll
    for (int i = 0; i < 4; i++) {
        m_i[i] = -1e30f; l_i[i] = 0.0f;
#pragma unroll
        for (int j = 0; j < 8; j++) O[i][j] = 0.0f;
    }

    for (int kb = 0; kb <= qb; kb++) {
        __syncthreads();   // previous PV done; Q stores visible on first iter

        // Load K tile transposed -> Kst[d][token], and V tile -> Vs[token][d]
#pragma unroll
        for (int it = 0; it < 8; it++) {
            int f = tid + it * 256;
            int row = f >> 5;            // token within block: 0..63
            int cv = (f & 31) << 2;      // d: 0..124
            size_t gk = (size_t)(kb * 64 + row) * QKV_O + Q_END + kvh * HD_ + cv;
            float4 kv4 = *(const float4*)&qkv[gk];
            Kst[(cv + 0) * KT_STRIDE + row] = kv4.x;
            Kst[(cv + 1) * KT_STRIDE + row] = kv4.y;
            Kst[(cv + 2) * KT_STRIDE + row] = kv4.z;
            Kst[(cv + 3) * KT_STRIDE + row] = kv4.w;
            size_t gv = (size_t)(kb * 64 + row) * QKV_O + K_END + kvh * HD_ + cv;
            float4 vv4 = *(const float4*)&qkv[gv];
            *(float4*)&Vs[row * VS_STRIDE + cv] = vv4;
        }
        __syncthreads();

        // S = Q K^T  (4x4 per thread)
        float s[4][4];
#pragma unroll
        for (int i = 0; i < 4; i++)
#pragma unroll
            for (int j = 0; j < 4; j++) s[i][j] = 0.0f;

#pragma unroll 4
        for (int k = 0; k < 128; k++) {
            float q0v = Qs[(tr * 4 + 0) * QS_STRIDE + k];
            float q1v = Qs[(tr * 4 + 1) * QS_STRIDE + k];
            float q2v = Qs[(tr * 4 + 2) * QS_STRIDE + k];
            float q3v = Qs[(tr * 4 + 3) * QS_STRIDE + k];
            float4 kk = *(const float4*)&Kst[k * KT_STRIDE + tc * 4];
            s[0][0] = fmaf(q0v, kk.x, s[0][0]); s[0][1] = fmaf(q0v, kk.y, s[0][1]);
            s[0][2] = fmaf(q0v, kk.z, s[0][2]); s[0][3] = fmaf(q0v, kk.w, s[0][3]);
            s[1][0] = fmaf(q1v, kk.x, s[1][0]); s[1][1] = fmaf(q1v, kk.y, s[1][1]);
            s[1][2] = fmaf(q1v, kk.z, s[1][2]); s[1][3] = fmaf(q1v, kk.w, s[1][3]);
            s[2][0] = fmaf(q2v, kk.x, s[2][0]); s[2][1] = fmaf(q2v, kk.y, s[2][1]);
            s[2][2] = fmaf(q2v, kk.z, s[2][2]); s[2][3] = fmaf(q2v, kk.w, s[2][3]);
            s[3][0] = fmaf(q3v, kk.x, s[3][0]); s[3][1] = fmaf(q3v, kk.y, s[3][1]);
            s[3][2] = fmaf(q3v, kk.z, s[3][2]); s[3][3] = fmaf(q3v, kk.w, s[3][3]);
        }

        // scale + causal mask (only diagonal block needs it)
        if (kb == qb) {
#pragma unroll
            for (int i = 0; i < 4; i++) {
                int qi = tr * 4 + i;
#pragma unroll
                for (int j = 0; j < 4; j++) {
                    int kj = tc * 4 + j;
                    s[i][j] = (kj <= qi) ? s[i][j] * scale : -1e30f;
                }
            }
        } else {
#pragma unroll
            for (int i = 0; i < 4; i++)
#pragma unroll
                for (int j = 0; j < 4; j++) s[i][j] *= scale;
        }

        // online softmax: row reductions across the 16 tc threads (16-lane group)
        float rmax[4], rsum[4];
#pragma unroll
        for (int i = 0; i < 4; i++) {
            float mx = fmaxf(fmaxf(s[i][0], s[i][1]), fmaxf(s[i][2], s[i][3]));
#pragma unroll
            for (int off = 8; off >= 1; off >>= 1)
                mx = fmaxf(mx, __shfl_xor_sync(0xffffffffu, mx, off));
            rmax[i] = mx;
        }

#pragma unroll
        for (int i = 0; i < 4; i++) {
            float m_new = fmaxf(m_i[i], rmax[i]);
            float alpha = expf(m_i[i] - m_new);
            float sum = 0.0f;
#pragma unroll
            for (int j = 0; j < 4; j++) {
                s[i][j] = expf(s[i][j] - m_new);   // now holds P
                sum += s[i][j];
            }
#pragma unroll
            for (int off = 8; off >= 1; off >>= 1)
                sum += __shfl_xor_sync(0xffffffffu, sum, off);
            rsum[i] = sum;
            l_i[i] = l_i[i] * alpha + rsum[i];
            m_i[i] = m_new;
#pragma unroll
            for (int j = 0; j < 8; j++) O[i][j] *= alpha;
        }

        // store P tile
#pragma unroll
        for (int i = 0; i < 4; i++) {
            float4 p4 = make_float4(s[i][0], s[i][1], s[i][2], s[i][3]);
            *(float4*)&Ps[(tr * 4 + i) * PS_STRIDE + tc * 4] = p4;
        }
        __syncthreads();

        // O += P V   (4x8 per thread)
#pragma unroll 4
        for (int k = 0; k < 64; k++) {
            float p0 = Ps[(tr * 4 + 0) * PS_STRIDE + k];
            float p1 = Ps[(tr * 4 + 1) * PS_STRIDE + k];
            float p2 = Ps[(tr * 4 + 2) * PS_STRIDE + k];
            float p3 = Ps[(tr * 4 + 3) * PS_STRIDE + k];
            float4 v0 = *(const float4*)&Vs[k * VS_STRIDE + tc * 8];
            float4 v1 = *(const float4*)&Vs[k * VS_STRIDE + tc * 8 + 4];
            float vv[8] = {v0.x, v0.y, v0.z, v0.w, v1.x, v1.y, v1.z, v1.w};
#pragma unroll
            for (int j = 0; j < 8; j++) {
                O[0][j] = fmaf(p0, vv[j], O[0][j]);
                O[1][j] = fmaf(p1, vv[j], O[1][j]);
                O[2][j] = fmaf(p2, vv[j], O[2][j]);
                O[3][j] = fmaf(p3, vv[j], O[3][j]);
            }
        }
    }

    // finalize + write: attn_out[(q0+row), head*128 + col]
#pragma unroll
    for (int i = 0; i < 4; i++) {
        float inv_l = 1.0f / l_i[i];
        float* orow = &attn_out[(size_t)(q0 + tr * 4 + i) * H_ + head * HD_ + tc * 8];
        float4 o0 = make_float4(O[i][0] * inv_l, O[i][1] * inv_l,
                                O[i][2] * inv_l, O[i][3] * inv_l);
        float4 o1 = make_float4(O[i][4] * inv_l, O[i][5] * inv_l,
                                O[i][6] * inv_l, O[i][7] * inv_l);
        *(float4*)&orow[0] = o0;
        *(float4*)&orow[4] = o1;
    }
}

// ---------------------------------------------------------------------------
extern "C" void kernel_launch(void* const* d_in, const int* in_sizes, int n_in,
                              void* d_out, int out_size)
{
    const float* hidden = (const float*)d_in[0];   // [1,2048,4096]
    const float* Wqkv   = (const float*)d_in[1];   // [6144,4096]
    const float* Wo     = (const float*)d_in[2];   // [4096,4096]
    float* out = (float*)d_out;                    // [1,2048,4096]

    float* qkv_ptr = nullptr;
    float* attn_ptr = nullptr;
    cudaGetSymbolAddress((void**)&qkv_ptr, g_qkv);
    cudaGetSymbolAddress((void**)&attn_ptr, g_attn);

    // 1) QKV projection: [2048,6144] = hidden[2048,4096] * Wqkv[6144,4096]^T
    {
        dim3 grid(QKV_O / 128, S_ / 128);
        sgemm_nt_kernel<<<grid, 256>>>(hidden, Wqkv, qkv_ptr, S_, QKV_O, H_);
    }

    // 2) RoPE on q,k in place
    {
        int total = S_ * (NH_ + NKV_) * (HD_ / 2);
        rope_kernel<<<(total + 255) / 256, 256>>>(qkv_ptr);
    }

    // 3) Flash attention
    {
        static int smem_set = 0;
        size_t smem_bytes = SMEM_FLOATS * sizeof(float);
        cudaFuncSetAttribute(flash_attn_kernel,
                             cudaFuncAttributeMaxDynamicSharedMemorySize,
                             (int)smem_bytes);
        dim3 grid(S_ / 64, NH_);
        flash_attn_kernel<<<grid, 256, smem_bytes>>>(qkv_ptr, attn_ptr);
        (void)smem_set;
    }

    // 4) Output projection: out[2048,4096] = attn[2048,4096] * Wo[4096,4096]^T
    {
        dim3 grid(H_ / 128, S_ / 128);
        sgemm_nt_kernel<<<grid, 256>>>(attn_ptr, Wo, out, S_, H_, H_);
    }
}

// round 3
// speedup vs baseline: 1.6149x; 1.6149x over previous
#include <cuda_runtime.h>
#include <cuda_bf16.h>
#include <math.h>
#include <stdint.h>

// Problem constants
#define B_      1
#define S_      2048
#define H_      4096
#define NH_     32
#define NKV_    8
#define HD_     128
#define QKV_O   ((NH_ + 2 * NKV_) * HD_)   // 6144
#define Q_END   (NH_ * HD_)                // 4096
#define K_END   (Q_END + NKV_ * HD_)       // 5120

// ---------------------------------------------------------------------------
// Scratch (no allocations allowed)
// ---------------------------------------------------------------------------
__device__ float g_qkv[S_ * QKV_O];     // fp32 QKV   [2048, 6144]
__device__ float g_attn[S_ * H_];       // fp32 attn  [2048, 4096]

__device__ __nv_bfloat16 g_hid_hi[S_ * H_];
__device__ __nv_bfloat16 g_hid_lo[S_ * H_];
__device__ __nv_bfloat16 g_wqkv_hi[QKV_O * H_];
__device__ __nv_bfloat16 g_wqkv_lo[QKV_O * H_];
__device__ __nv_bfloat16 g_wo_hi[H_ * H_];
__device__ __nv_bfloat16 g_wo_lo[H_ * H_];
__device__ __nv_bfloat16 g_attn_hi[S_ * H_];
__device__ __nv_bfloat16 g_attn_lo[S_ * H_];

// ---------------------------------------------------------------------------
// Baseline-ISA PTX helpers (all sm_80+/sm_75+ — safe for compute_103 target)
// ---------------------------------------------------------------------------
__device__ __forceinline__ uint32_t smem_u32(const void* p) {
    uint32_t a;
    asm("{ .reg .u64 t; cvta.to.shared.u64 t, %1; cvt.u32.u64 %0, t; }"
        : "=r"(a) : "l"(p));
    return a;
}

#define CP_ASYNC16(dst, src) \
    asm volatile("cp.async.cg.shared.global [%0], [%1], 16;" \
        :: "r"(dst), "l"(src) : "memory")
#define CP_COMMIT() asm volatile("cp.async.commit_group;" ::: "memory")
#define CP_WAIT(n)  asm volatile("cp.async.wait_group %0;" :: "n"(n) : "memory")

#define LDSM_X4(r0, r1, r2, r3, addr) \
    asm volatile("ldmatrix.sync.aligned.m8n8.x4.shared.b16 {%0,%1,%2,%3}, [%4];" \
        : "=r"(r0), "=r"(r1), "=r"(r2), "=r"(r3) : "r"(addr))

#define MMA_BF16(d, a, b0, b1) \
    asm volatile("mma.sync.aligned.m16n8k16.row.col.f32.bf16.bf16.f32 " \
        "{%0,%1,%2,%3}, {%4,%5,%6,%7}, {%8,%9}, {%0,%1,%2,%3};" \
        : "+f"((d)[0]), "+f"((d)[1]), "+f"((d)[2]), "+f"((d)[3]) \
        : "r"((a)[0]), "r"((a)[1]), "r"((a)[2]), "r"((a)[3]), "r"(b0), "r"(b1))

// ---------------------------------------------------------------------------
// fp32 -> (bf16 hi, bf16 lo) split conversion. n4 = n/4 float4 groups.
// ---------------------------------------------------------------------------
__global__ void cvt_split_kernel(const float* __restrict__ x,
                                 __nv_bfloat16* __restrict__ hi,
                                 __nv_bfloat16* __restrict__ lo, int n4)
{
    int i = blockIdx.x * blockDim.x + threadIdx.x;
    if (i >= n4) return;
    float4 v = ((const float4*)x)[i];
    __nv_bfloat16 h0 = __float2bfloat16_rn(v.x);
    __nv_bfloat16 h1 = __float2bfloat16_rn(v.y);
    __nv_bfloat16 h2 = __float2bfloat16_rn(v.z);
    __nv_bfloat16 h3 = __float2bfloat16_rn(v.w);
    __nv_bfloat16 l0 = __float2bfloat16_rn(v.x - __bfloat162float(h0));
    __nv_bfloat16 l1 = __float2bfloat16_rn(v.y - __bfloat162float(h1));
    __nv_bfloat16 l2 = __float2bfloat16_rn(v.z - __bfloat162float(h2));
    __nv_bfloat16 l3 = __float2bfloat16_rn(v.w - __bfloat162float(h3));
    ((__nv_bfloat162*)hi)[i * 2 + 0] = __nv_bfloat162(h0, h1);
    ((__nv_bfloat162*)hi)[i * 2 + 1] = __nv_bfloat162(h2, h3);
    ((__nv_bfloat162*)lo)[i * 2 + 0] = __nv_bfloat162(l0, l1);
    ((__nv_bfloat162*)lo)[i * 2 + 1] = __nv_bfloat162(l2, l3);
}

// ---------------------------------------------------------------------------
// bf16x3 GEMM via mma.sync (HMMA):  C[M,N] = A[M,K] * B[N,K]^T  (fp32-accurate)
// CTA tile 128x128, BK=32. 8 warps; each warp: 64x32 (4 m-tiles x 4 n-tiles).
// SMEM per stage: Ahi|Alo|Bhi|Blo, each 128 rows x 80B (64B data + 16B pad),
// double-buffered via cp.async.
// ---------------------------------------------------------------------------
#define TILE_B   10240              // 128 * 80
#define STAGE_B  (4 * TILE_B)       // 40960
#define GEMM_SMEM_BYTES (2 * STAGE_B)

__global__ __launch_bounds__(256, 1) void gemm_mma_kernel(
    const __nv_bfloat16* __restrict__ Ahi, const __nv_bfloat16* __restrict__ Alo,
    const __nv_bfloat16* __restrict__ Bhi, const __nv_bfloat16* __restrict__ Blo,
    float* __restrict__ C, int N, int K)
{
    extern __shared__ __align__(128) char smem[];
    const uint32_t sbase = smem_u32(smem);
    const int tid = threadIdx.x;
    const int wid = tid >> 5;
    const int lane = tid & 31;
    const int m0 = blockIdx.y * 128;
    const int n0 = blockIdx.x * 128;
    const int NC = K / 32;

    const int warp_m = wid & 1;        // 0..1  (64 rows each)
    const int warp_n = wid >> 1;       // 0..3  (32 cols each)

    const __nv_bfloat16* srcs[4] = {Ahi, Alo, Bhi, Blo};
    const int row0s[4] = {m0, m0, n0, n0};

    // ldmatrix lane decomposition
    const int q = lane >> 3;           // matrix index 0..3
    const int r = lane & 7;            // row within 8x8 matrix

    float acc[4][4][4];
#pragma unroll
    for (int mt = 0; mt < 4; mt++)
#pragma unroll
        for (int nt = 0; nt < 4; nt++)
#pragma unroll
            for (int e = 0; e < 4; e++) acc[mt][nt][e] = 0.0f;

    auto load_stage = [&](int stage, int c) {
        const uint32_t st = sbase + (uint32_t)stage * STAGE_B;
#pragma unroll
        for (int i = 0; i < 8; i++) {
            int g = tid + i * 256;          // 0..2047
            int sel = g >> 9;               // tile 0..3
            int rem = g & 511;
            int row = rem >> 2;             // 0..127
            int u = rem & 3;                // 16B unit
            const char* gsrc = (const char*)(srcs[sel] + (size_t)(row0s[sel] + row) * K)
                               + c * 64 + u * 16;
            uint32_t dst = st + (uint32_t)sel * TILE_B + (uint32_t)(row * 80 + u * 16);
            CP_ASYNC16(dst, gsrc);
        }
        CP_COMMIT();
    };

    load_stage(0, 0);

    for (int c = 0; c < NC; c++) {
        if (c + 1 < NC) {
            load_stage((c + 1) & 1, c + 1);
            CP_WAIT(1);
        } else {
            CP_WAIT(0);
        }
        __syncthreads();

        const uint32_t st = sbase + (uint32_t)(c & 1) * STAGE_B;
        const uint32_t aBase = st;                 // Ahi; Alo at +TILE_B
        const uint32_t bBase = st + 2 * TILE_B;    // Bhi; Blo at +TILE_B

#pragma unroll
        for (int kstep = 0; kstep < 2; kstep++) {
            uint32_t ahi[4][4], alo[4][4];
            const int aunit = kstep * 2 + (q >> 1);
#pragma unroll
            for (int mt = 0; mt < 4; mt++) {
                int row = warp_m * 64 + mt * 16 + (q & 1) * 8 + r;
                uint32_t addr = aBase + (uint32_t)(row * 80 + aunit * 16);
                LDSM_X4(ahi[mt][0], ahi[mt][1], ahi[mt][2], ahi[mt][3], addr);
                LDSM_X4(alo[mt][0], alo[mt][1], alo[mt][2], alo[mt][3], addr + TILE_B);
            }
            uint32_t bhi[2][4], blo[2][4];
            const int bunit = kstep * 2 + (q & 1);
#pragma unroll
            for (int np = 0; np < 2; np++) {
                int brow = warp_n * 32 + np * 16 + (q >> 1) * 8 + r;
                uint32_t addr = bBase + (uint32_t)(brow * 80 + bunit * 16);
                LDSM_X4(bhi[np][0], bhi[np][1], bhi[np][2], bhi[np][3], addr);
                LDSM_X4(blo[np][0], blo[np][1], blo[np][2], blo[np][3], addr + TILE_B);
            }
#pragma unroll
            for (int mt = 0; mt < 4; mt++) {
#pragma unroll
                for (int nt = 0; nt < 4; nt++) {
                    const int np = nt >> 1, hv = (nt & 1) * 2;
                    MMA_BF16(acc[mt][nt], ahi[mt], bhi[np][hv], bhi[np][hv + 1]);
                    MMA_BF16(acc[mt][nt], ahi[mt], blo[np][hv], blo[np][hv + 1]);
                    MMA_BF16(acc[mt][nt], alo[mt], bhi[np][hv], bhi[np][hv + 1]);
                }
            }
        }
        __syncthreads();
    }

    // Epilogue: direct global stores (float2 per fragment half)
    const int gp = lane >> 2;          // 0..7
    const int tg = lane & 3;           // 0..3
#pragma unroll
    for (int mt = 0; mt < 4; mt++) {
#pragma unroll
        for (int nt = 0; nt < 4; nt++) {
            int row = m0 + warp_m * 64 + mt * 16 + gp;
            int col = n0 + warp_n * 32 + nt * 8 + tg * 2;
            *(float2*)&C[(size_t)row * N + col] =
                make_float2(acc[mt][nt][0], acc[mt][nt][1]);
            *(float2*)&C[(size_t)(row + 8) * N + col] =
                make_float2(acc[mt][nt][2], acc[mt][nt][3]);
        }
    }
}

// ---------------------------------------------------------------------------
// RoPE applied in place to q (heads 0..31) and k (heads 32..39) of g_qkv.
// ---------------------------------------------------------------------------
__global__ void rope_kernel(float* __restrict__ qkv)
{
    int idx = blockIdx.x * blockDim.x + threadIdx.x;
    const int total = S_ * (NH_ + NKV_) * (HD_ / 2);
    if (idx >= total) return;
    int d2 = idx & 63;
    int t = idx >> 6;
    int head = t % (NH_ + NKV_);
    int s = t / (NH_ + NKV_);

    double inv = exp(-((double)(2 * d2) / (double)HD_) * 9.210340371976184);
    double ang = (double)s * inv;
    double sv, cv;
    sincos(ang, &sv, &cv);
    float c = (float)cv, sn = (float)sv;

    size_t base = (size_t)s * QKV_O + head * HD_;
    float x1 = qkv[base + d2];
    float x2 = qkv[base + 64 + d2];
    qkv[base + d2]      = x1 * c - x2 * sn;
    qkv[base + 64 + d2] = x1 * sn + x2 * c;
}

// ---------------------------------------------------------------------------
// Flash attention, fp32, causal, GQA (unchanged from round 1).
// ---------------------------------------------------------------------------
#define QS_STRIDE 132
#define KT_STRIDE 68
#define VS_STRIDE 132
#define PS_STRIDE 68
#define SMEM_FLOATS (64*QS_STRIDE + 128*KT_STRIDE + 64*VS_STRIDE + 64*PS_STRIDE)

__global__ __launch_bounds__(256) void flash_attn_kernel(
    const float* __restrict__ qkv, float* __restrict__ attn_out)
{
    extern __shared__ float sm[];
    float* Qs  = sm;
    float* Kst = Qs + 64 * QS_STRIDE;
    float* Vs  = Kst + 128 * KT_STRIDE;
    float* Ps  = Vs + 64 * VS_STRIDE;

    const int qb   = blockIdx.x;
    const int head = blockIdx.y;
    const int kvh  = head >> 2;
    const int tid  = threadIdx.x;
    const int tr   = tid / 16;
    const int tc   = tid % 16;
    const int q0   = qb * 64;
    const float scale = 0.08838834764831845f;

#pragma unroll
    for (int it = 0; it < 8; it++) {
        int f = tid + it * 256;
        int row = f >> 5;
        int cv = (f & 31) << 2;
        float4 v = *(const float4*)&qkv[(size_t)(q0 + row) * QKV_O + head * HD_ + cv];
        *(float4*)&Qs[row * QS_STRIDE + cv] = v;
    }

    float O[4][8];
    float m_i[4], l_i[4];
#pragma unroll
    for (int i = 0; i < 4; i++) {
        m_i[i] = -1e30f; l_i[i] = 0.0f;
#pragma unroll
        for (int j = 0; j < 8; j++) O[i][j] = 0.0f;
    }

    for (int kb = 0; kb <= qb; kb++) {
        __syncthreads();
#pragma unroll
        for (int it = 0; it < 8; it++) {
            int f = tid + it * 256;
            int row = f >> 5;
            int cv = (f & 31) << 2;
            size_t gk = (size_t)(kb * 64 + row) * QKV_O + Q_END + kvh * HD_ + cv;
            float4 kv4 = *(const float4*)&qkv[gk];
            Kst[(cv + 0) * KT_STRIDE + row] = kv4.x;
            Kst[(cv + 1) * KT_STRIDE + row] = kv4.y;
            Kst[(cv + 2) * KT_STRIDE + row] = kv4.z;
            Kst[(cv + 3) * KT_STRIDE + row] = kv4.w;
            size_t gv = (size_t)(kb * 64 + row) * QKV_O + K_END + kvh * HD_ + cv;
            float4 vv4 = *(const float4*)&qkv[gv];
            *(float4*)&Vs[row * VS_STRIDE + cv] = vv4;
        }
        __syncthreads();

        float s[4][4];
#pragma unroll
        for (int i = 0; i < 4; i++)
#pragma unroll
            for (int j = 0; j < 4; j++) s[i][j] = 0.0f;

#pragma unroll 4
        for (int k = 0; k < 128; k++) {
            float q0v = Qs[(tr * 4 + 0) * QS_STRIDE + k];
            float q1v = Qs[(tr * 4 + 1) * QS_STRIDE + k];
            float q2v = Qs[(tr * 4 + 2) * QS_STRIDE + k];
            float q3v = Qs[(tr * 4 + 3) * QS_STRIDE + k];
            float4 kk = *(const float4*)&Kst[k * KT_STRIDE + tc * 4];
            s[0][0] = fmaf(q0v, kk.x, s[0][0]); s[0][1] = fmaf(q0v, kk.y, s[0][1]);
            s[0][2] = fmaf(q0v, kk.z, s[0][2]); s[0][3] = fmaf(q0v, kk.w, s[0][3]);
            s[1][0] = fmaf(q1v, kk.x, s[1][0]); s[1][1] = fmaf(q1v, kk.y, s[1][1]);
            s[1][2] = fmaf(q1v, kk.z, s[1][2]); s[1][3] = fmaf(q1v, kk.w, s[1][3]);
            s[2][0] = fmaf(q2v, kk.x, s[2][0]); s[2][1] = fmaf(q2v, kk.y, s[2][1]);
            s[2][2] = fmaf(q2v, kk.z, s[2][2]); s[2][3] = fmaf(q2v, kk.w, s[2][3]);
            s[3][0] = fmaf(q3v, kk.x, s[3][0]); s[3][1] = fmaf(q3v, kk.y, s[3][1]);
            s[3][2] = fmaf(q3v, kk.z, s[3][2]); s[3][3] = fmaf(q3v, kk.w, s[3][3]);
        }

        if (kb == qb) {
#pragma unroll
            for (int i = 0; i < 4; i++) {
                int qi = tr * 4 + i;
#pragma unroll
                for (int j = 0; j < 4; j++) {
                    int kj = tc * 4 + j;
                    s[i][j] = (kj <= qi) ? s[i][j] * scale : -1e30f;
                }
            }
        } else {
#pragma unroll
            for (int i = 0; i < 4; i++)
#pragma unroll
                for (int j = 0; j < 4; j++) s[i][j] *= scale;
        }

        float rmax[4];
#pragma unroll
        for (int i = 0; i < 4; i++) {
            float mx = fmaxf(fmaxf(s[i][0], s[i][1]), fmaxf(s[i][2], s[i][3]));
#pragma unroll
            for (int off = 8; off >= 1; off >>= 1)
                mx = fmaxf(mx, __shfl_xor_sync(0xffffffffu, mx, off));
            rmax[i] = mx;
        }

#pragma unroll
        for (int i = 0; i < 4; i++) {
            float m_new = fmaxf(m_i[i], rmax[i]);
            float alpha = expf(m_i[i] - m_new);
            float sum = 0.0f;
#pragma unroll
            for (int j = 0; j < 4; j++) {
                s[i][j] = expf(s[i][j] - m_new);
                sum += s[i][j];
            }
#pragma unroll
            for (int off = 8; off >= 1; off >>= 1)
                sum += __shfl_xor_sync(0xffffffffu, sum, off);
            l_i[i] = l_i[i] * alpha + sum;
            m_i[i] = m_new;
#pragma unroll
            for (int j = 0; j < 8; j++) O[i][j] *= alpha;
        }

#pragma unroll
        for (int i = 0; i < 4; i++) {
            float4 p4 = make_float4(s[i][0], s[i][1], s[i][2], s[i][3]);
            *(float4*)&Ps[(tr * 4 + i) * PS_STRIDE + tc * 4] = p4;
        }
        __syncthreads();

#pragma unroll 4
        for (int k = 0; k < 64; k++) {
            float p0 = Ps[(tr * 4 + 0) * PS_STRIDE + k];
            float p1 = Ps[(tr * 4 + 1) * PS_STRIDE + k];
            float p2 = Ps[(tr * 4 + 2) * PS_STRIDE + k];
            float p3 = Ps[(tr * 4 + 3) * PS_STRIDE + k];
            float4 v0 = *(const float4*)&Vs[k * VS_STRIDE + tc * 8];
            float4 v1 = *(const float4*)&Vs[k * VS_STRIDE + tc * 8 + 4];
            float vv[8] = {v0.x, v0.y, v0.z, v0.w, v1.x, v1.y, v1.z, v1.w};
#pragma unroll
            for (int j = 0; j < 8; j++) {
                O[0][j] = fmaf(p0, vv[j], O[0][j]);
                O[1][j] = fmaf(p1, vv[j], O[1][j]);
                O[2][j] = fmaf(p2, vv[j], O[2][j]);
                O[3][j] = fmaf(p3, vv[j], O[3][j]);
            }
        }
    }

#pragma unroll
    for (int i = 0; i < 4; i++) {
        float inv_l = 1.0f / l_i[i];
        float* orow = &attn_out[(size_t)(q0 + tr * 4 + i) * H_ + head * HD_ + tc * 8];
        float4 o0 = make_float4(O[i][0] * inv_l, O[i][1] * inv_l,
                                O[i][2] * inv_l, O[i][3] * inv_l);
        float4 o1 = make_float4(O[i][4] * inv_l, O[i][5] * inv_l,
                                O[i][6] * inv_l, O[i][7] * inv_l);
        *(float4*)&orow[0] = o0;
        *(float4*)&orow[4] = o1;
    }
}

// ---------------------------------------------------------------------------
extern "C" void kernel_launch(void* const* d_in, const int* in_sizes, int n_in,
                              void* d_out, int out_size)
{
    const float* hidden = (const float*)d_in[0];   // [1,2048,4096]
    const float* Wqkv   = (const float*)d_in[1];   // [6144,4096]
    const float* Wo     = (const float*)d_in[2];   // [4096,4096]
    float* out = (float*)d_out;                    // [1,2048,4096]

    float* qkv_ptr = nullptr;  float* attn_ptr = nullptr;
    __nv_bfloat16 *hid_hi, *hid_lo, *wqkv_hi, *wqkv_lo, *wo_hi, *wo_lo, *attn_hi, *attn_lo;
    cudaGetSymbolAddress((void**)&qkv_ptr, g_qkv);
    cudaGetSymbolAddress((void**)&attn_ptr, g_attn);
    cudaGetSymbolAddress((void**)&hid_hi, g_hid_hi);
    cudaGetSymbolAddress((void**)&hid_lo, g_hid_lo);
    cudaGetSymbolAddress((void**)&wqkv_hi, g_wqkv_hi);
    cudaGetSymbolAddress((void**)&wqkv_lo, g_wqkv_lo);
    cudaGetSymbolAddress((void**)&wo_hi, g_wo_hi);
    cudaGetSymbolAddress((void**)&wo_lo, g_wo_lo);
    cudaGetSymbolAddress((void**)&attn_hi, g_attn_hi);
    cudaGetSymbolAddress((void**)&attn_lo, g_attn_lo);

    cudaFuncSetAttribute(gemm_mma_kernel,
                         cudaFuncAttributeMaxDynamicSharedMemorySize, GEMM_SMEM_BYTES);
    cudaFuncSetAttribute(flash_attn_kernel,
                         cudaFuncAttributeMaxDynamicSharedMemorySize,
                         (int)(SMEM_FLOATS * sizeof(float)));

    // 0) split-convert inputs to bf16 hi/lo
    {
        int n4;
        n4 = (S_ * H_) / 4;
        cvt_split_kernel<<<(n4 + 255) / 256, 256>>>(hidden, hid_hi, hid_lo, n4);
        n4 = (QKV_O * H_) / 4;
        cvt_split_kernel<<<(n4 + 255) / 256, 256>>>(Wqkv, wqkv_hi, wqkv_lo, n4);
        n4 = (H_ * H_) / 4;
        cvt_split_kernel<<<(n4 + 255) / 256, 256>>>(Wo, wo_hi, wo_lo, n4);
    }

    // 1) QKV projection (HMMA bf16x3): [2048,6144]
    {
        dim3 grid(QKV_O / 128, S_ / 128);
        gemm_mma_kernel<<<grid, 256, GEMM_SMEM_BYTES>>>(
            hid_hi, hid_lo, wqkv_hi, wqkv_lo, qkv_ptr, QKV_O, H_);
    }

    // 2) RoPE in place
    {
        int total = S_ * (NH_ + NKV_) * (HD_ / 2);
        rope_kernel<<<(total + 255) / 256, 256>>>(qkv_ptr);
    }

    // 3) Flash attention
    {
        dim3 grid(S_ / 64, NH_);
        flash_attn_kernel<<<grid, 256, SMEM_FLOATS * sizeof(float)>>>(qkv_ptr, attn_ptr);
    }

    // 4) split-convert attention output
    {
        int n4 = (S_ * H_) / 4;
        cvt_split_kernel<<<(n4 + 255) / 256, 256>>>(attn_ptr, attn_hi, attn_lo, n4);
    }

    // 5) Output projection (HMMA bf16x3): [2048,4096]
    {
        dim3 grid(H_ / 128, S_ / 128);
        gemm_mma_kernel<<<grid, 256, GEMM_SMEM_BYTES>>>(
            attn_hi, attn_lo, wo_hi, wo_lo, out, H_, H_);
    }
}

// round 4
// speedup vs baseline: 2.7464x; 1.7007x over previous
#include <cuda_runtime.h>
#include <cuda_bf16.h>
#include <math.h>
#include <stdint.h>

// Problem constants
#define B_      1
#define S_      2048
#define H_      4096
#define NH_     32
#define NKV_    8
#define HD_     128
#define QKV_O   ((NH_ + 2 * NKV_) * HD_)   // 6144
#define Q_END   (NH_ * HD_)                // 4096
#define K_END   (Q_END + NKV_ * HD_)       // 5120

// ---------------------------------------------------------------------------
// Scratch (no allocations allowed)
// ---------------------------------------------------------------------------
__device__ float g_qkv[S_ * QKV_O];     // fp32 QKV   [2048, 6144]
__device__ float g_attn[S_ * H_];       // fp32 attn  [2048, 4096]

__device__ __nv_bfloat16 g_hid_hi[S_ * H_];
__device__ __nv_bfloat16 g_hid_lo[S_ * H_];
__device__ __nv_bfloat16 g_wqkv_hi[QKV_O * H_];
__device__ __nv_bfloat16 g_wqkv_lo[QKV_O * H_];
__device__ __nv_bfloat16 g_wo_hi[H_ * H_];
__device__ __nv_bfloat16 g_wo_lo[H_ * H_];
__device__ __nv_bfloat16 g_attn_hi[S_ * H_];
__device__ __nv_bfloat16 g_attn_lo[S_ * H_];

__device__ __nv_bfloat16 g_q_hi[S_ * H_];            // RoPE'd Q  [2048, 4096]
__device__ __nv_bfloat16 g_q_lo[S_ * H_];
__device__ __nv_bfloat16 g_k_hi[S_ * NKV_ * HD_];    // RoPE'd K  [2048, 1024]
__device__ __nv_bfloat16 g_k_lo[S_ * NKV_ * HD_];
__device__ __nv_bfloat16 g_v_hi[S_ * NKV_ * HD_];    // V         [2048, 1024]
__device__ __nv_bfloat16 g_v_lo[S_ * NKV_ * HD_];

// ---------------------------------------------------------------------------
// Baseline-ISA PTX helpers
// ---------------------------------------------------------------------------
__device__ __forceinline__ uint32_t smem_u32(const void* p) {
    uint32_t a;
    asm("{ .reg .u64 t; cvta.to.shared.u64 t, %1; cvt.u32.u64 %0, t; }"
        : "=r"(a) : "l"(p));
    return a;
}

#define CP_ASYNC16(dst, src) \
    asm volatile("cp.async.cg.shared.global [%0], [%1], 16;" \
        :: "r"(dst), "l"(src) : "memory")
#define CP_COMMIT() asm volatile("cp.async.commit_group;" ::: "memory")
#define CP_WAIT(n)  asm volatile("cp.async.wait_group %0;" :: "n"(n) : "memory")

#define LDSM_X4(r0, r1, r2, r3, addr) \
    asm volatile("ldmatrix.sync.aligned.m8n8.x4.shared.b16 {%0,%1,%2,%3}, [%4];" \
        : "=r"(r0), "=r"(r1), "=r"(r2), "=r"(r3) : "r"(addr))

#define LDSM_X4_T(r0, r1, r2, r3, addr) \
    asm volatile("ldmatrix.sync.aligned.m8n8.x4.trans.shared.b16 {%0,%1,%2,%3}, [%4];" \
        : "=r"(r0), "=r"(r1), "=r"(r2), "=r"(r3) : "r"(addr))

#define MMA_BF16(d, a, b0, b1) \
    asm volatile("mma.sync.aligned.m16n8k16.row.col.f32.bf16.bf16.f32 " \
        "{%0,%1,%2,%3}, {%4,%5,%6,%7}, {%8,%9}, {%0,%1,%2,%3};" \
        : "+f"((d)[0]), "+f"((d)[1]), "+f"((d)[2]), "+f"((d)[3]) \
        : "r"((a)[0]), "r"((a)[1]), "r"((a)[2]), "r"((a)[3]), "r"(b0), "r"(b1))

__device__ __forceinline__ uint32_t pack_bf16(float x, float y) {
    __nv_bfloat162 h = __floats2bfloat162_rn(x, y);
    return *(uint32_t*)&h;
}

// ---------------------------------------------------------------------------
// fp32 -> (bf16 hi, bf16 lo) split conversion. n4 = n/4 float4 groups.
// ---------------------------------------------------------------------------
__global__ void cvt_split_kernel(const float* __restrict__ x,
                                 __nv_bfloat16* __restrict__ hi,
                                 __nv_bfloat16* __restrict__ lo, int n4)
{
    int i = blockIdx.x * blockDim.x + threadIdx.x;
    if (i >= n4) return;
    float4 v = ((const float4*)x)[i];
    __nv_bfloat16 h0 = __float2bfloat16_rn(v.x);
    __nv_bfloat16 h1 = __float2bfloat16_rn(v.y);
    __nv_bfloat16 h2 = __float2bfloat16_rn(v.z);
    __nv_bfloat16 h3 = __float2bfloat16_rn(v.w);
    __nv_bfloat16 l0 = __float2bfloat16_rn(v.x - __bfloat162float(h0));
    __nv_bfloat16 l1 = __float2bfloat16_rn(v.y - __bfloat162float(h1));
    __nv_bfloat16 l2 = __float2bfloat16_rn(v.z - __bfloat162float(h2));
    __nv_bfloat16 l3 = __float2bfloat16_rn(v.w - __bfloat162float(h3));
    ((__nv_bfloat162*)hi)[i * 2 + 0] = __nv_bfloat162(h0, h1);
    ((__nv_bfloat162*)hi)[i * 2 + 1] = __nv_bfloat162(h2, h3);
    ((__nv_bfloat162*)lo)[i * 2 + 0] = __nv_bfloat162(l0, l1);
    ((__nv_bfloat162*)lo)[i * 2 + 1] = __nv_bfloat162(l2, l3);
}

// ---------------------------------------------------------------------------
// bf16x3 GEMM via mma.sync (HMMA):  C[M,N] = A[M,K] * B[N,K]^T
// ---------------------------------------------------------------------------
#define TILE_B   10240              // 128 * 80
#define STAGE_B  (4 * TILE_B)       // 40960
#define GEMM_SMEM_BYTES (2 * STAGE_B)

__global__ __launch_bounds__(256, 1) void gemm_mma_kernel(
    const __nv_bfloat16* __restrict__ Ahi, const __nv_bfloat16* __restrict__ Alo,
    const __nv_bfloat16* __restrict__ Bhi, const __nv_bfloat16* __restrict__ Blo,
    float* __restrict__ C, int N, int K)
{
    extern __shared__ __align__(128) char smem[];
    const uint32_t sbase = smem_u32(smem);
    const int tid = threadIdx.x;
    const int wid = tid >> 5;
    const int lane = tid & 31;
    const int m0 = blockIdx.y * 128;
    const int n0 = blockIdx.x * 128;
    const int NC = K / 32;

    const int warp_m = wid & 1;
    const int warp_n = wid >> 1;

    const __nv_bfloat16* srcs[4] = {Ahi, Alo, Bhi, Blo};
    const int row0s[4] = {m0, m0, n0, n0};

    const int q = lane >> 3;
    const int r = lane & 7;

    float acc[4][4][4];
#pragma unroll
    for (int mt = 0; mt < 4; mt++)
#pragma unroll
        for (int nt = 0; nt < 4; nt++)
#pragma unroll
            for (int e = 0; e < 4; e++) acc[mt][nt][e] = 0.0f;

    auto load_stage = [&](int stage, int c) {
        const uint32_t st = sbase + (uint32_t)stage * STAGE_B;
#pragma unroll
        for (int i = 0; i < 8; i++) {
            int g = tid + i * 256;
            int sel = g >> 9;
            int rem = g & 511;
            int row = rem >> 2;
            int u = rem & 3;
            const char* gsrc = (const char*)(srcs[sel] + (size_t)(row0s[sel] + row) * K)
                               + c * 64 + u * 16;
            uint32_t dst = st + (uint32_t)sel * TILE_B + (uint32_t)(row * 80 + u * 16);
            CP_ASYNC16(dst, gsrc);
        }
        CP_COMMIT();
    };

    load_stage(0, 0);

    for (int c = 0; c < NC; c++) {
        if (c + 1 < NC) {
            load_stage((c + 1) & 1, c + 1);
            CP_WAIT(1);
        } else {
            CP_WAIT(0);
        }
        __syncthreads();

        const uint32_t st = sbase + (uint32_t)(c & 1) * STAGE_B;
        const uint32_t aBase = st;
        const uint32_t bBase = st + 2 * TILE_B;

#pragma unroll
        for (int kstep = 0; kstep < 2; kstep++) {
            uint32_t ahi[4][4], alo[4][4];
            const int aunit = kstep * 2 + (q >> 1);
#pragma unroll
            for (int mt = 0; mt < 4; mt++) {
                int row = warp_m * 64 + mt * 16 + (q & 1) * 8 + r;
                uint32_t addr = aBase + (uint32_t)(row * 80 + aunit * 16);
                LDSM_X4(ahi[mt][0], ahi[mt][1], ahi[mt][2], ahi[mt][3], addr);
                LDSM_X4(alo[mt][0], alo[mt][1], alo[mt][2], alo[mt][3], addr + TILE_B);
            }
            uint32_t bhi[2][4], blo[2][4];
            const int bunit = kstep * 2 + (q & 1);
#pragma unroll
            for (int np = 0; np < 2; np++) {
                int brow = warp_n * 32 + np * 16 + (q >> 1) * 8 + r;
                uint32_t addr = bBase + (uint32_t)(brow * 80 + bunit * 16);
                LDSM_X4(bhi[np][0], bhi[np][1], bhi[np][2], bhi[np][3], addr);
                LDSM_X4(blo[np][0], blo[np][1], blo[np][2], blo[np][3], addr + TILE_B);
            }
#pragma unroll
            for (int mt = 0; mt < 4; mt++) {
#pragma unroll
                for (int nt = 0; nt < 4; nt++) {
                    const int np = nt >> 1, hv = (nt & 1) * 2;
                    MMA_BF16(acc[mt][nt], ahi[mt], bhi[np][hv], bhi[np][hv + 1]);
                    MMA_BF16(acc[mt][nt], ahi[mt], blo[np][hv], blo[np][hv + 1]);
                    MMA_BF16(acc[mt][nt], alo[mt], bhi[np][hv], bhi[np][hv + 1]);
                }
            }
        }
        __syncthreads();
    }

    const int gp = lane >> 2;
    const int tg = lane & 3;
#pragma unroll
    for (int mt = 0; mt < 4; mt++) {
#pragma unroll
        for (int nt = 0; nt < 4; nt++) {
            int row = m0 + warp_m * 64 + mt * 16 + gp;
            int col = n0 + warp_n * 32 + nt * 8 + tg * 2;
            *(float2*)&C[(size_t)row * N + col] =
                make_float2(acc[mt][nt][0], acc[mt][nt][1]);
            *(float2*)&C[(size_t)(row + 8) * N + col] =
                make_float2(acc[mt][nt][2], acc[mt][nt][3]);
        }
    }
}

// ---------------------------------------------------------------------------
// RoPE + bf16 hi/lo conversion of Q,K.  One block per sequence position s.
// Threads 0..63 compute the sincos table (double) once; then 256 threads
// process 40 heads x 64 pairs.
// ---------------------------------------------------------------------------
__global__ __launch_bounds__(256) void rope_cvt_kernel(
    const float* __restrict__ qkv,
    __nv_bfloat16* __restrict__ qhi, __nv_bfloat16* __restrict__ qlo,
    __nv_bfloat16* __restrict__ khi, __nv_bfloat16* __restrict__ klo)
{
    __shared__ float cs[64], sn[64];
    const int s = blockIdx.x;
    const int tid = threadIdx.x;
    if (tid < 64) {
        double inv = exp(-((double)(2 * tid) / (double)HD_) * 9.210340371976184);
        double ang = (double)s * inv;
        double sv, cv;
        sincos(ang, &sv, &cv);
        cs[tid] = (float)cv;
        sn[tid] = (float)sv;
    }
    __syncthreads();

    // 40 heads * 64 pairs = 2560 work items; 256 threads -> 10 each
#pragma unroll
    for (int it = 0; it < 10; it++) {
        int g = tid + it * 256;
        int d2 = g & 63;
        int head = g >> 6;          // 0..39
        size_t base = (size_t)s * QKV_O + head * HD_;
        float x1 = qkv[base + d2];
        float x2 = qkv[base + 64 + d2];
        float c = cs[d2], si = sn[d2];
        float y1 = x1 * c - x2 * si;
        float y2 = x1 * si + x2 * c;

        __nv_bfloat16 h1 = __float2bfloat16_rn(y1);
        __nv_bfloat16 l1 = __float2bfloat16_rn(y1 - __bfloat162float(h1));
        __nv_bfloat16 h2 = __float2bfloat16_rn(y2);
        __nv_bfloat16 l2 = __float2bfloat16_rn(y2 - __bfloat162float(h2));

        if (head < NH_) {
            size_t o = (size_t)s * H_ + head * HD_;
            qhi[o + d2] = h1; qlo[o + d2] = l1;
            qhi[o + 64 + d2] = h2; qlo[o + 64 + d2] = l2;
        } else {
            size_t o = (size_t)s * (NKV_ * HD_) + (head - NH_) * HD_;
            khi[o + d2] = h1; klo[o + d2] = l1;
            khi[o + 64 + d2] = h2; klo[o + 64 + d2] = l2;
        }
    }
}

// V: strided split-convert out of g_qkv
__global__ void v_cvt_kernel(const float* __restrict__ qkv,
                             __nv_bfloat16* __restrict__ vhi,
                             __nv_bfloat16* __restrict__ vlo)
{
    int i = blockIdx.x * blockDim.x + threadIdx.x;   // over S_*1024/4
    const int n4 = S_ * NKV_ * HD_ / 4;
    if (i >= n4) return;
    int s = i >> 8;             // 1024/4 = 256 groups per row
    int col = (i & 255) * 4;
    const float* src = qkv + (size_t)s * QKV_O + K_END + col;
    float4 v = *(const float4*)src;
    __nv_bfloat16 h0 = __float2bfloat16_rn(v.x);
    __nv_bfloat16 h1 = __float2bfloat16_rn(v.y);
    __nv_bfloat16 h2 = __float2bfloat16_rn(v.z);
    __nv_bfloat16 h3 = __float2bfloat16_rn(v.w);
    size_t o = (size_t)s * (NKV_ * HD_) + col;
    *(__nv_bfloat162*)(vhi + o)     = __nv_bfloat162(h0, h1);
    *(__nv_bfloat162*)(vhi + o + 2) = __nv_bfloat162(h2, h3);
    *(__nv_bfloat162*)(vlo + o) = __nv_bfloat162(
        __float2bfloat16_rn(v.x - __bfloat162float(h0)),
        __float2bfloat16_rn(v.y - __bfloat162float(h1)));
    *(__nv_bfloat162*)(vlo + o + 2) = __nv_bfloat162(
        __float2bfloat16_rn(v.z - __bfloat162float(h2)),
        __float2bfloat16_rn(v.w - __bfloat162float(h3)));
}

// ---------------------------------------------------------------------------
// Flash attention via mma.sync, bf16x3 QK^T and bf16x3 PV, causal, GQA.
// BQ=64 (4 warps x 16 rows), BK=32, D=128.
// SMEM pitch 272B (136 bf16) -> conflict-free ldmatrix.
// Layout: Qhi(17408) Qlo(17408) | 2 stages x [Khi Klo Vhi Vlo](8704 each)
// ---------------------------------------------------------------------------
#define AP_ 136                     // pitch in bf16 elements
#define APB_ 272                    // pitch bytes
#define Q_COMP_B 17408              // 64 * 272
#define KV_COMP_B 8704              // 32 * 272
#define KV_STAGE_B (4 * KV_COMP_B)  // 34816
#define ATTN_SMEM_BYTES (2 * Q_COMP_B + 2 * KV_STAGE_B)   // 104448

__global__ __launch_bounds__(128, 2) void flash_attn_mma_kernel(
    const __nv_bfloat16* __restrict__ qhi, const __nv_bfloat16* __restrict__ qlo,
    const __nv_bfloat16* __restrict__ khi, const __nv_bfloat16* __restrict__ klo,
    const __nv_bfloat16* __restrict__ vhi, const __nv_bfloat16* __restrict__ vlo,
    float* __restrict__ attn_out)
{
    extern __shared__ __align__(128) char smA[];
    const uint32_t sb = smem_u32(smA);
    const int qb = gridDim.x - 1 - blockIdx.x;   // heavy blocks first
    const int head = blockIdx.y;
    const int kvh = head >> 2;
    const int tid = threadIdx.x;
    const int wid = tid >> 5;
    const int lane = tid & 31;
    const int gp = lane >> 2;
    const int tg = lane & 3;
    const int q0 = qb * 64;

    const uint32_t Qhi_s = sb;
    const uint32_t Qlo_s = sb + Q_COMP_B;
    const uint32_t Stage_s = sb + 2 * Q_COMP_B;

    // ---- load Q (commit group 0): 2 comps x 64 rows x 16 units
#pragma unroll
    for (int i = 0; i < 16; i++) {
        int g = tid + i * 128;
        int comp = g >> 10;
        int rem = g & 1023;
        int row = rem >> 4;
        int u = rem & 15;
        const __nv_bfloat16* src = (comp ? qlo : qhi)
            + (size_t)(q0 + row) * H_ + head * HD_ + u * 8;
        uint32_t dst = (comp ? Qlo_s : Qhi_s) + (uint32_t)(row * APB_ + u * 16);
        CP_ASYNC16(dst, src);
    }
    CP_COMMIT();

    const int kb_max = 2 * qb + 1;

    auto load_kv = [&](int stage, int kb) {
        uint32_t st = Stage_s + (uint32_t)stage * KV_STAGE_B;
        const __nv_bfloat16* bases[4] = {khi, klo, vhi, vlo};
#pragma unroll
        for (int i = 0; i < 16; i++) {
            int g = tid + i * 128;
            int comp = g >> 9;
            int rem = g & 511;
            int row = rem >> 4;
            int u = rem & 15;
            const __nv_bfloat16* src = bases[comp]
                + (size_t)(kb * 32 + row) * (NKV_ * HD_) + kvh * HD_ + u * 8;
            CP_ASYNC16(st + (uint32_t)(comp * KV_COMP_B + row * APB_ + u * 16), src);
        }
        CP_COMMIT();
    };

    load_kv(0, 0);

    float O[16][4];
    float m_i[2] = {-1e30f, -1e30f};
    float l_i[2] = {0.0f, 0.0f};
#pragma unroll
    for (int nt = 0; nt < 16; nt++)
#pragma unroll
        for (int e = 0; e < 4; e++) O[nt][e] = 0.0f;

    const float scale = 0.08838834764831845f;

    for (int kb = 0; kb <= kb_max; kb++) {
        if (kb < kb_max) { load_kv((kb + 1) & 1, kb + 1); CP_WAIT(1); }
        else             { CP_WAIT(0); }
        __syncthreads();

        const uint32_t st = Stage_s + (uint32_t)(kb & 1) * KV_STAGE_B;
        const uint32_t Ks_hi = st;
        const uint32_t Ks_lo = st + KV_COMP_B;
        const uint32_t Vs_hi = st + 2 * KV_COMP_B;
        const uint32_t Vs_lo = st + 3 * KV_COMP_B;

        // ---- S = Q K^T : 4 n-tiles (n8) x 8 k-tiles, bf16x3
        float S[4][4];
#pragma unroll
        for (int t = 0; t < 4; t++)
#pragma unroll
            for (int e = 0; e < 4; e++) S[t][e] = 0.0f;

#pragma unroll
        for (int kt = 0; kt < 8; kt++) {
            uint32_t aoff = (uint32_t)((wid * 16 + (lane & 15)) * APB_
                                       + (kt * 16 + (lane >> 4) * 8) * 2);
            uint32_t ahi[4], alo[4];
            LDSM_X4(ahi[0], ahi[1], ahi[2], ahi[3], Qhi_s + aoff);
            LDSM_X4(alo[0], alo[1], alo[2], alo[3], Qlo_s + aoff);
#pragma unroll
            for (int pr = 0; pr < 2; pr++) {
                uint32_t boff = (uint32_t)((pr * 16 + (lane >> 4) * 8 + (lane & 7)) * APB_
                                           + (kt * 16 + ((lane >> 3) & 1) * 8) * 2);
                uint32_t bh[4], bl[4];
                LDSM_X4(bh[0], bh[1], bh[2], bh[3], Ks_hi + boff);
                LDSM_X4(bl[0], bl[1], bl[2], bl[3], Ks_lo + boff);
                MMA_BF16(S[2 * pr],     ahi, bh[0], bh[1]);
                MMA_BF16(S[2 * pr],     ahi, bl[0], bl[1]);
                MMA_BF16(S[2 * pr],     alo, bh[0], bh[1]);
                MMA_BF16(S[2 * pr + 1], ahi, bh[2], bh[3]);
                MMA_BF16(S[2 * pr + 1], ahi, bl[2], bl[3]);
                MMA_BF16(S[2 * pr + 1], alo, bh[2], bh[3]);
            }
        }

        // ---- scale + causal mask
        if (kb >= 2 * qb) {
#pragma unroll
            for (int t = 0; t < 4; t++) {
                int colb = kb * 32 + t * 8 + 2 * tg;
#pragma unroll
                for (int e = 0; e < 4; e++) {
                    int col = colb + (e & 1);
                    int row = q0 + wid * 16 + gp + ((e >= 2) ? 8 : 0);
                    S[t][e] = (col <= row) ? S[t][e] * scale : -1e30f;
                }
            }
        } else {
#pragma unroll
            for (int t = 0; t < 4; t++)
#pragma unroll
                for (int e = 0; e < 4; e++) S[t][e] *= scale;
        }

        // ---- online softmax (two row-halves per thread)
#pragma unroll
        for (int h = 0; h < 2; h++) {
            float mx = -1e30f;
#pragma unroll
            for (int t = 0; t < 4; t++)
                mx = fmaxf(mx, fmaxf(S[t][2 * h], S[t][2 * h + 1]));
            mx = fmaxf(mx, __shfl_xor_sync(0xffffffffu, mx, 1));
            mx = fmaxf(mx, __shfl_xor_sync(0xffffffffu, mx, 2));
            float m_new = fmaxf(m_i[h], mx);
            float alpha = __expf(m_i[h] - m_new);
            float sum = 0.0f;
#pragma unroll
            for (int t = 0; t < 4; t++) {
                S[t][2 * h]     = __expf(S[t][2 * h] - m_new);
                S[t][2 * h + 1] = __expf(S[t][2 * h + 1] - m_new);
                sum += S[t][2 * h] + S[t][2 * h + 1];
            }
            sum += __shfl_xor_sync(0xffffffffu, sum, 1);
            sum += __shfl_xor_sync(0xffffffffu, sum, 2);
            l_i[h] = l_i[h] * alpha + sum;
            m_i[h] = m_new;
#pragma unroll
            for (int nt = 0; nt < 16; nt++) {
                O[nt][2 * h] *= alpha;
                O[nt][2 * h + 1] *= alpha;
            }
        }

        // ---- O += P V : P split hi/lo, V split hi/lo (3 MMAs)
#pragma unroll
        for (int kt2 = 0; kt2 < 2; kt2++) {
            uint32_t phi[4], plo[4];
            {
                float* p0 = S[2 * kt2];
                float* p1 = S[2 * kt2 + 1];
                float h00 = __bfloat162float(__float2bfloat16_rn(p0[0]));
                float h01 = __bfloat162float(__float2bfloat16_rn(p0[1]));
                float h02 = __bfloat162float(__float2bfloat16_rn(p0[2]));
                float h03 = __bfloat162float(__float2bfloat16_rn(p0[3]));
                float h10 = __bfloat162float(__float2bfloat16_rn(p1[0]));
                float h11 = __bfloat162float(__float2bfloat16_rn(p1[1]));
                float h12 = __bfloat162float(__float2bfloat16_rn(p1[2]));
                float h13 = __bfloat162float(__float2bfloat16_rn(p1[3]));
                phi[0] = pack_bf16(h00, h01);
                phi[1] = pack_bf16(h02, h03);
                phi[2] = pack_bf16(h10, h11);
                phi[3] = pack_bf16(h12, h13);
                plo[0] = pack_bf16(p0[0] - h00, p0[1] - h01);
                plo[1] = pack_bf16(p0[2] - h02, p0[3] - h03);
                plo[2] = pack_bf16(p1[0] - h10, p1[1] - h11);
                plo[3] = pack_bf16(p1[2] - h12, p1[3] - h13);
            }
#pragma unroll
            for (int dp = 0; dp < 8; dp++) {
                uint32_t voff = (uint32_t)((kt2 * 16 + ((lane >> 3) & 1) * 8 + (lane & 7)) * APB_
                                           + (dp * 16 + (lane >> 4) * 8) * 2);
                uint32_t bh[4], bl[4];
                LDSM_X4_T(bh[0], bh[1], bh[2], bh[3], Vs_hi + voff);
                LDSM_X4_T(bl[0], bl[1], bl[2], bl[3], Vs_lo + voff);
                MMA_BF16(O[2 * dp],     phi, bh[0], bh[1]);
                MMA_BF16(O[2 * dp],     phi, bl[0], bl[1]);
                MMA_BF16(O[2 * dp],     plo, bh[0], bh[1]);
                MMA_BF16(O[2 * dp + 1], phi, bh[2], bh[3]);
                MMA_BF16(O[2 * dp + 1], phi, bl[2], bl[3]);
                MMA_BF16(O[2 * dp + 1], plo, bh[2], bh[3]);
            }
        }
        __syncthreads();
    }

    // ---- finalize + write
#pragma unroll
    for (int h = 0; h < 2; h++) {
        float inv = 1.0f / l_i[h];
        int row = q0 + wid * 16 + gp + h * 8;
        float* orow = attn_out + (size_t)row * H_ + head * HD_;
#pragma unroll
        for (int nt = 0; nt < 16; nt++) {
            *(float2*)&orow[nt * 8 + 2 * tg] =
                make_float2(O[nt][2 * h] * inv, O[nt][2 * h + 1] * inv);
        }
    }
}

// ---------------------------------------------------------------------------
extern "C" void kernel_launch(void* const* d_in, const int* in_sizes, int n_in,
                              void* d_out, int out_size)
{
    const float* hidden = (const float*)d_in[0];   // [1,2048,4096]
    const float* Wqkv   = (const float*)d_in[1];   // [6144,4096]
    const float* Wo     = (const float*)d_in[2];   // [4096,4096]
    float* out = (float*)d_out;                    // [1,2048,4096]

    float* qkv_ptr = nullptr;  float* attn_ptr = nullptr;
    __nv_bfloat16 *hid_hi, *hid_lo, *wqkv_hi, *wqkv_lo, *wo_hi, *wo_lo, *attn_hi, *attn_lo;
    __nv_bfloat16 *q_hi, *q_lo, *k_hi, *k_lo, *v_hi, *v_lo;
    cudaGetSymbolAddress((void**)&qkv_ptr, g_qkv);
    cudaGetSymbolAddress((void**)&attn_ptr, g_attn);
    cudaGetSymbolAddress((void**)&hid_hi, g_hid_hi);
    cudaGetSymbolAddress((void**)&hid_lo, g_hid_lo);
    cudaGetSymbolAddress((void**)&wqkv_hi, g_wqkv_hi);
    cudaGetSymbolAddress((void**)&wqkv_lo, g_wqkv_lo);
    cudaGetSymbolAddress((void**)&wo_hi, g_wo_hi);
    cudaGetSymbolAddress((void**)&wo_lo, g_wo_lo);
    cudaGetSymbolAddress((void**)&attn_hi, g_attn_hi);
    cudaGetSymbolAddress((void**)&attn_lo, g_attn_lo);
    cudaGetSymbolAddress((void**)&q_hi, g_q_hi);
    cudaGetSymbolAddress((void**)&q_lo, g_q_lo);
    cudaGetSymbolAddress((void**)&k_hi, g_k_hi);
    cudaGetSymbolAddress((void**)&k_lo, g_k_lo);
    cudaGetSymbolAddress((void**)&v_hi, g_v_hi);
    cudaGetSymbolAddress((void**)&v_lo, g_v_lo);

    cudaFuncSetAttribute(gemm_mma_kernel,
                         cudaFuncAttributeMaxDynamicSharedMemorySize, GEMM_SMEM_BYTES);
    cudaFuncSetAttribute(flash_attn_mma_kernel,
                         cudaFuncAttributeMaxDynamicSharedMemorySize, ATTN_SMEM_BYTES);

    // 0) split-convert inputs
    {
        int n4;
        n4 = (S_ * H_) / 4;
        cvt_split_kernel<<<(n4 + 255) / 256, 256>>>(hidden, hid_hi, hid_lo, n4);
        n4 = (QKV_O * H_) / 4;
        cvt_split_kernel<<<(n4 + 255) / 256, 256>>>(Wqkv, wqkv_hi, wqkv_lo, n4);
        n4 = (H_ * H_) / 4;
        cvt_split_kernel<<<(n4 + 255) / 256, 256>>>(Wo, wo_hi, wo_lo, n4);
    }

    // 1) QKV projection (HMMA bf16x3)
    {
        dim3 grid(QKV_O / 128, S_ / 128);
        gemm_mma_kernel<<<grid, 256, GEMM_SMEM_BYTES>>>(
            hid_hi, hid_lo, wqkv_hi, wqkv_lo, qkv_ptr, QKV_O, H_);
    }

    // 2) RoPE + split-convert Q,K; split-convert V
    {
        rope_cvt_kernel<<<S_, 256>>>(qkv_ptr, q_hi, q_lo, k_hi, k_lo);
        int n4 = (S_ * NKV_ * HD_) / 4;
        v_cvt_kernel<<<(n4 + 255) / 256, 256>>>(qkv_ptr, v_hi, v_lo);
    }

    // 3) Flash attention (HMMA bf16x3)
    {
        dim3 grid(S_ / 64, NH_);
        flash_attn_mma_kernel<<<grid, 128, ATTN_SMEM_BYTES>>>(
            q_hi, q_lo, k_hi, k_lo, v_hi, v_lo, attn_ptr);
    }

    // 4) split-convert attention output
    {
        int n4 = (S_ * H_) / 4;
        cvt_split_kernel<<<(n4 + 255) / 256, 256>>>(attn_ptr, attn_hi, attn_lo, n4);
    }

    // 5) Output projection (HMMA bf16x3)
    {
        dim3 grid(H_ / 128, S_ / 128);
        gemm_mma_kernel<<<grid, 256, GEMM_SMEM_BYTES>>>(
            attn_hi, attn_lo, wo_hi, wo_lo, out, H_, H_);
    }
}

// round 5
// speedup vs baseline: 3.1184x; 1.1355x over previous
#include <cuda_runtime.h>
#include <cuda_bf16.h>
#include <math.h>
#include <stdint.h>

// Problem constants
#define B_      1
#define S_      2048
#define H_      4096
#define NH_     32
#define NKV_    8
#define HD_     128
#define QKV_O   ((NH_ + 2 * NKV_) * HD_)   // 6144
#define Q_END   (NH_ * HD_)                // 4096
#define K_END   (Q_END + NKV_ * HD_)       // 5120

// ---------------------------------------------------------------------------
// Scratch (no allocations allowed)
// ---------------------------------------------------------------------------
__device__ float g_qkv[S_ * QKV_O];     // fp32 QKV   [2048, 6144]

__device__ __nv_bfloat16 g_hid_hi[S_ * H_];
__device__ __nv_bfloat16 g_hid_lo[S_ * H_];
__device__ __nv_bfloat16 g_wqkv_hi[QKV_O * H_];
__device__ __nv_bfloat16 g_wqkv_lo[QKV_O * H_];
__device__ __nv_bfloat16 g_wo_hi[H_ * H_];
__device__ __nv_bfloat16 g_wo_lo[H_ * H_];
__device__ __nv_bfloat16 g_attn_hi[S_ * H_];
__device__ __nv_bfloat16 g_attn_lo[S_ * H_];

__device__ __nv_bfloat16 g_q_hi[S_ * H_];            // RoPE'd Q  [2048, 4096]
__device__ __nv_bfloat16 g_q_lo[S_ * H_];
__device__ __nv_bfloat16 g_k_hi[S_ * NKV_ * HD_];    // RoPE'd K  [2048, 1024]
__device__ __nv_bfloat16 g_k_lo[S_ * NKV_ * HD_];
__device__ __nv_bfloat16 g_v_hi[S_ * NKV_ * HD_];    // V         [2048, 1024]
__device__ __nv_bfloat16 g_v_lo[S_ * NKV_ * HD_];

// ---------------------------------------------------------------------------
// Baseline-ISA PTX helpers
// ---------------------------------------------------------------------------
__device__ __forceinline__ uint32_t smem_u32(const void* p) {
    uint32_t a;
    asm("{ .reg .u64 t; cvta.to.shared.u64 t, %1; cvt.u32.u64 %0, t; }"
        : "=r"(a) : "l"(p));
    return a;
}

#define CP_ASYNC16(dst, src) \
    asm volatile("cp.async.cg.shared.global [%0], [%1], 16;" \
        :: "r"(dst), "l"(src) : "memory")
#define CP_COMMIT() asm volatile("cp.async.commit_group;" ::: "memory")
#define CP_WAIT(n)  asm volatile("cp.async.wait_group %0;" :: "n"(n) : "memory")

#define LDSM_X4(r0, r1, r2, r3, addr) \
    asm volatile("ldmatrix.sync.aligned.m8n8.x4.shared.b16 {%0,%1,%2,%3}, [%4];" \
        : "=r"(r0), "=r"(r1), "=r"(r2), "=r"(r3) : "r"(addr))

#define LDSM_X4_T(r0, r1, r2, r3, addr) \
    asm volatile("ldmatrix.sync.aligned.m8n8.x4.trans.shared.b16 {%0,%1,%2,%3}, [%4];" \
        : "=r"(r0), "=r"(r1), "=r"(r2), "=r"(r3) : "r"(addr))

#define MMA_BF16(d, a, b0, b1) \
    asm volatile("mma.sync.aligned.m16n8k16.row.col.f32.bf16.bf16.f32 " \
        "{%0,%1,%2,%3}, {%4,%5,%6,%7}, {%8,%9}, {%0,%1,%2,%3};" \
        : "+f"((d)[0]), "+f"((d)[1]), "+f"((d)[2]), "+f"((d)[3]) \
        : "r"((a)[0]), "r"((a)[1]), "r"((a)[2]), "r"((a)[3]), "r"(b0), "r"(b1))

__device__ __forceinline__ uint32_t pack_bf16(float x, float y) {
    __nv_bfloat162 h = __floats2bfloat162_rn(x, y);
    return *(uint32_t*)&h;
}

// ---------------------------------------------------------------------------
// fp32 -> (bf16 hi, bf16 lo) split conversion. n4 = n/4 float4 groups.
// ---------------------------------------------------------------------------
__global__ void cvt_split_kernel(const float* __restrict__ x,
                                 __nv_bfloat16* __restrict__ hi,
                                 __nv_bfloat16* __restrict__ lo, int n4)
{
    int i = blockIdx.x * blockDim.x + threadIdx.x;
    if (i >= n4) return;
    float4 v = ((const float4*)x)[i];
    __nv_bfloat16 h0 = __float2bfloat16_rn(v.x);
    __nv_bfloat16 h1 = __float2bfloat16_rn(v.y);
    __nv_bfloat16 h2 = __float2bfloat16_rn(v.z);
    __nv_bfloat16 h3 = __float2bfloat16_rn(v.w);
    __nv_bfloat16 l0 = __float2bfloat16_rn(v.x - __bfloat162float(h0));
    __nv_bfloat16 l1 = __float2bfloat16_rn(v.y - __bfloat162float(h1));
    __nv_bfloat16 l2 = __float2bfloat16_rn(v.z - __bfloat162float(h2));
    __nv_bfloat16 l3 = __float2bfloat16_rn(v.w - __bfloat162float(h3));
    ((__nv_bfloat162*)hi)[i * 2 + 0] = __nv_bfloat162(h0, h1);
    ((__nv_bfloat162*)hi)[i * 2 + 1] = __nv_bfloat162(h2, h3);
    ((__nv_bfloat162*)lo)[i * 2 + 0] = __nv_bfloat162(l0, l1);
    ((__nv_bfloat162*)lo)[i * 2 + 1] = __nv_bfloat162(l2, l3);
}

// ---------------------------------------------------------------------------
// bf16x3 GEMM via mma.sync (HMMA):  C[M,N] = A[M,K] * B[N,K]^T
// 1-D grid, m-fastest tile order (L2-friendly B reuse).
// __launch_bounds__(256, 2) -> 2 CTAs/SM.
// ---------------------------------------------------------------------------
#define TILE_B   10240              // 128 * 80
#define STAGE_B  (4 * TILE_B)       // 40960
#define GEMM_SMEM_BYTES (2 * STAGE_B)

__global__ __launch_bounds__(256, 2) void gemm_mma_kernel(
    const __nv_bfloat16* __restrict__ Ahi, const __nv_bfloat16* __restrict__ Alo,
    const __nv_bfloat16* __restrict__ Bhi, const __nv_bfloat16* __restrict__ Blo,
    float* __restrict__ C, int N, int K, int Mtiles)
{
    extern __shared__ __align__(128) char smem[];
    const uint32_t sbase = smem_u32(smem);
    const int tid = threadIdx.x;
    const int wid = tid >> 5;
    const int lane = tid & 31;
    const int m0 = (blockIdx.x % Mtiles) * 128;
    const int n0 = (blockIdx.x / Mtiles) * 128;
    const int NC = K / 32;

    const int warp_m = wid & 1;
    const int warp_n = wid >> 1;

    const __nv_bfloat16* srcs[4] = {Ahi, Alo, Bhi, Blo};
    const int row0s[4] = {m0, m0, n0, n0};

    const int q = lane >> 3;
    const int r = lane & 7;

    float acc[4][4][4];
#pragma unroll
    for (int mt = 0; mt < 4; mt++)
#pragma unroll
        for (int nt = 0; nt < 4; nt++)
#pragma unroll
            for (int e = 0; e < 4; e++) acc[mt][nt][e] = 0.0f;

    auto load_stage = [&](int stage, int c) {
        const uint32_t st = sbase + (uint32_t)stage * STAGE_B;
#pragma unroll
        for (int i = 0; i < 8; i++) {
            int g = tid + i * 256;
            int sel = g >> 9;
            int rem = g & 511;
            int row = rem >> 2;
            int u = rem & 3;
            const char* gsrc = (const char*)(srcs[sel] + (size_t)(row0s[sel] + row) * K)
                               + c * 64 + u * 16;
            uint32_t dst = st + (uint32_t)sel * TILE_B + (uint32_t)(row * 80 + u * 16);
            CP_ASYNC16(dst, gsrc);
        }
        CP_COMMIT();
    };

    load_stage(0, 0);

    for (int c = 0; c < NC; c++) {
        if (c + 1 < NC) {
            load_stage((c + 1) & 1, c + 1);
            CP_WAIT(1);
        } else {
            CP_WAIT(0);
        }
        __syncthreads();

        const uint32_t st = sbase + (uint32_t)(c & 1) * STAGE_B;
        const uint32_t aBase = st;
        const uint32_t bBase = st + 2 * TILE_B;

#pragma unroll
        for (int kstep = 0; kstep < 2; kstep++) {
            // B fragments first (kept live through the mt loop): 16 regs
            uint32_t bh0[4], bh1[4], bl0[4], bl1[4];
            const int bunit = kstep * 2 + (q & 1);
            {
                int brow0 = warp_n * 32 + (q >> 1) * 8 + r;
                uint32_t a0 = bBase + (uint32_t)(brow0 * 80 + bunit * 16);
                LDSM_X4(bh0[0], bh0[1], bh0[2], bh0[3], a0);
                LDSM_X4(bl0[0], bl0[1], bl0[2], bl0[3], a0 + TILE_B);
                uint32_t a1 = a0 + 16 * 80;
                LDSM_X4(bh1[0], bh1[1], bh1[2], bh1[3], a1);
                LDSM_X4(bl1[0], bl1[1], bl1[2], bl1[3], a1 + TILE_B);
            }
            const int aunit = kstep * 2 + (q >> 1);
#pragma unroll
            for (int mt = 0; mt < 4; mt++) {
                uint32_t ah[4], al[4];
                int row = warp_m * 64 + mt * 16 + (q & 1) * 8 + r;
                uint32_t addr = aBase + (uint32_t)(row * 80 + aunit * 16);
                LDSM_X4(ah[0], ah[1], ah[2], ah[3], addr);
                LDSM_X4(al[0], al[1], al[2], al[3], addr + TILE_B);

                MMA_BF16(acc[mt][0], ah, bh0[0], bh0[1]);
                MMA_BF16(acc[mt][0], ah, bl0[0], bl0[1]);
                MMA_BF16(acc[mt][0], al, bh0[0], bh0[1]);
                MMA_BF16(acc[mt][1], ah, bh0[2], bh0[3]);
                MMA_BF16(acc[mt][1], ah, bl0[2], bl0[3]);
                MMA_BF16(acc[mt][1], al, bh0[2], bh0[3]);
                MMA_BF16(acc[mt][2], ah, bh1[0], bh1[1]);
                MMA_BF16(acc[mt][2], ah, bl1[0], bl1[1]);
                MMA_BF16(acc[mt][2], al, bh1[0], bh1[1]);
                MMA_BF16(acc[mt][3], ah, bh1[2], bh1[3]);
                MMA_BF16(acc[mt][3], ah, bl1[2], bl1[3]);
                MMA_BF16(acc[mt][3], al, bh1[2], bh1[3]);
            }
        }
        __syncthreads();
    }

    const int gp = lane >> 2;
    const int tg = lane & 3;
#pragma unroll
    for (int mt = 0; mt < 4; mt++) {
#pragma unroll
        for (int nt = 0; nt < 4; nt++) {
            int row = m0 + warp_m * 64 + mt * 16 + gp;
            int col = n0 + warp_n * 32 + nt * 8 + tg * 2;
            *(float2*)&C[(size_t)row * N + col] =
                make_float2(acc[mt][nt][0], acc[mt][nt][1]);
            *(float2*)&C[(size_t)(row + 8) * N + col] =
                make_float2(acc[mt][nt][2], acc[mt][nt][3]);
        }
    }
}

// ---------------------------------------------------------------------------
// RoPE + bf16 hi/lo conversion of Q,K.  One block per sequence position s.
// ---------------------------------------------------------------------------
__global__ __launch_bounds__(256) void rope_cvt_kernel(
    const float* __restrict__ qkv,
    __nv_bfloat16* __restrict__ qhi, __nv_bfloat16* __restrict__ qlo,
    __nv_bfloat16* __restrict__ khi, __nv_bfloat16* __restrict__ klo)
{
    __shared__ float cs[64], sn[64];
    const int s = blockIdx.x;
    const int tid = threadIdx.x;
    if (tid < 64) {
        double inv = exp(-((double)(2 * tid) / (double)HD_) * 9.210340371976184);
        double ang = (double)s * inv;
        double sv, cv;
        sincos(ang, &sv, &cv);
        cs[tid] = (float)cv;
        sn[tid] = (float)sv;
    }
    __syncthreads();

#pragma unroll
    for (int it = 0; it < 10; it++) {
        int g = tid + it * 256;
        int d2 = g & 63;
        int head = g >> 6;          // 0..39
        size_t base = (size_t)s * QKV_O + head * HD_;
        float x1 = qkv[base + d2];
        float x2 = qkv[base + 64 + d2];
        float c = cs[d2], si = sn[d2];
        float y1 = x1 * c - x2 * si;
        float y2 = x1 * si + x2 * c;

        __nv_bfloat16 h1 = __float2bfloat16_rn(y1);
        __nv_bfloat16 l1 = __float2bfloat16_rn(y1 - __bfloat162float(h1));
        __nv_bfloat16 h2 = __float2bfloat16_rn(y2);
        __nv_bfloat16 l2 = __float2bfloat16_rn(y2 - __bfloat162float(h2));

        if (head < NH_) {
            size_t o = (size_t)s * H_ + head * HD_;
            qhi[o + d2] = h1; qlo[o + d2] = l1;
            qhi[o + 64 + d2] = h2; qlo[o + 64 + d2] = l2;
        } else {
            size_t o = (size_t)s * (NKV_ * HD_) + (head - NH_) * HD_;
            khi[o + d2] = h1; klo[o + d2] = l1;
            khi[o + 64 + d2] = h2; klo[o + 64 + d2] = l2;
        }
    }
}

// V: strided split-convert out of g_qkv
__global__ void v_cvt_kernel(const float* __restrict__ qkv,
                             __nv_bfloat16* __restrict__ vhi,
                             __nv_bfloat16* __restrict__ vlo)
{
    int i = blockIdx.x * blockDim.x + threadIdx.x;
    const int n4 = S_ * NKV_ * HD_ / 4;
    if (i >= n4) return;
    int s = i >> 8;
    int col = (i & 255) * 4;
    const float* src = qkv + (size_t)s * QKV_O + K_END + col;
    float4 v = *(const float4*)src;
    __nv_bfloat16 h0 = __float2bfloat16_rn(v.x);
    __nv_bfloat16 h1 = __float2bfloat16_rn(v.y);
    __nv_bfloat16 h2 = __float2bfloat16_rn(v.z);
    __nv_bfloat16 h3 = __float2bfloat16_rn(v.w);
    size_t o = (size_t)s * (NKV_ * HD_) + col;
    *(__nv_bfloat162*)(vhi + o)     = __nv_bfloat162(h0, h1);
    *(__nv_bfloat162*)(vhi + o + 2) = __nv_bfloat162(h2, h3);
    *(__nv_bfloat162*)(vlo + o) = __nv_bfloat162(
        __float2bfloat16_rn(v.x - __bfloat162float(h0)),
        __float2bfloat16_rn(v.y - __bfloat162float(h1)));
    *(__nv_bfloat162*)(vlo + o + 2) = __nv_bfloat162(
        __float2bfloat16_rn(v.z - __bfloat162float(h2)),
        __float2bfloat16_rn(v.w - __bfloat162float(h3)));
}

// ---------------------------------------------------------------------------
// Flash attention via mma.sync, bf16x3 QK^T and bf16x3 PV, causal, GQA.
// BQ=64 (4 warps x 16 rows), BK=32, D=128.  Epilogue writes hi/lo bf16 split
// directly (feeds output-projection GEMM).
// ---------------------------------------------------------------------------
#define AP_ 136
#define APB_ 272
#define Q_COMP_B 17408
#define KV_COMP_B 8704
#define KV_STAGE_B (4 * KV_COMP_B)
#define ATTN_SMEM_BYTES (2 * Q_COMP_B + 2 * KV_STAGE_B)   // 104448

__global__ __launch_bounds__(128, 2) void flash_attn_mma_kernel(
    const __nv_bfloat16* __restrict__ qhi, const __nv_bfloat16* __restrict__ qlo,
    const __nv_bfloat16* __restrict__ khi, const __nv_bfloat16* __restrict__ klo,
    const __nv_bfloat16* __restrict__ vhi, const __nv_bfloat16* __restrict__ vlo,
    __nv_bfloat16* __restrict__ out_hi, __nv_bfloat16* __restrict__ out_lo)
{
    extern __shared__ __align__(128) char smA[];
    const uint32_t sb = smem_u32(smA);
    const int qb = gridDim.x - 1 - blockIdx.x;   // heavy blocks first
    const int head = blockIdx.y;
    const int kvh = head >> 2;
    const int tid = threadIdx.x;
    const int wid = tid >> 5;
    const int lane = tid & 31;
    const int gp = lane >> 2;
    const int tg = lane & 3;
    const int q0 = qb * 64;

    const uint32_t Qhi_s = sb;
    const uint32_t Qlo_s = sb + Q_COMP_B;
    const uint32_t Stage_s = sb + 2 * Q_COMP_B;

#pragma unroll
    for (int i = 0; i < 16; i++) {
        int g = tid + i * 128;
        int comp = g >> 10;
        int rem = g & 1023;
        int row = rem >> 4;
        int u = rem & 15;
        const __nv_bfloat16* src = (comp ? qlo : qhi)
            + (size_t)(q0 + row) * H_ + head * HD_ + u * 8;
        uint32_t dst = (comp ? Qlo_s : Qhi_s) + (uint32_t)(row * APB_ + u * 16);
        CP_ASYNC16(dst, src);
    }
    CP_COMMIT();

    const int kb_max = 2 * qb + 1;

    auto load_kv = [&](int stage, int kb) {
        uint32_t st = Stage_s + (uint32_t)stage * KV_STAGE_B;
        const __nv_bfloat16* bases[4] = {khi, klo, vhi, vlo};
#pragma unroll
        for (int i = 0; i < 16; i++) {
            int g = tid + i * 128;
            int comp = g >> 9;
            int rem = g & 511;
            int row = rem >> 4;
            int u = rem & 15;
            const __nv_bfloat16* src = bases[comp]
                + (size_t)(kb * 32 + row) * (NKV_ * HD_) + kvh * HD_ + u * 8;
            CP_ASYNC16(st + (uint32_t)(comp * KV_COMP_B + row * APB_ + u * 16), src);
        }
        CP_COMMIT();
    };

    load_kv(0, 0);

    float O[16][4];
    float m_i[2] = {-1e30f, -1e30f};
    float l_i[2] = {0.0f, 0.0f};
#pragma unroll
    for (int nt = 0; nt < 16; nt++)
#pragma unroll
        for (int e = 0; e < 4; e++) O[nt][e] = 0.0f;

    const float scale = 0.08838834764831845f;

    for (int kb = 0; kb <= kb_max; kb++) {
        if (kb < kb_max) { load_kv((kb + 1) & 1, kb + 1); CP_WAIT(1); }
        else             { CP_WAIT(0); }
        __syncthreads();

        const uint32_t st = Stage_s + (uint32_t)(kb & 1) * KV_STAGE_B;
        const uint32_t Ks_hi = st;
        const uint32_t Ks_lo = st + KV_COMP_B;
        const uint32_t Vs_hi = st + 2 * KV_COMP_B;
        const uint32_t Vs_lo = st + 3 * KV_COMP_B;

        float S[4][4];
#pragma unroll
        for (int t = 0; t < 4; t++)
#pragma unroll
            for (int e = 0; e < 4; e++) S[t][e] = 0.0f;

#pragma unroll
        for (int kt = 0; kt < 8; kt++) {
            uint32_t aoff = (uint32_t)((wid * 16 + (lane & 15)) * APB_
                                       + (kt * 16 + (lane >> 4) * 8) * 2);
            uint32_t ahi[4], alo[4];
            LDSM_X4(ahi[0], ahi[1], ahi[2], ahi[3], Qhi_s + aoff);
            LDSM_X4(alo[0], alo[1], alo[2], alo[3], Qlo_s + aoff);
#pragma unroll
            for (int pr = 0; pr < 2; pr++) {
                uint32_t boff = (uint32_t)((pr * 16 + (lane >> 4) * 8 + (lane & 7)) * APB_
                                           + (kt * 16 + ((lane >> 3) & 1) * 8) * 2);
                uint32_t bh[4], bl[4];
                LDSM_X4(bh[0], bh[1], bh[2], bh[3], Ks_hi + boff);
                LDSM_X4(bl[0], bl[1], bl[2], bl[3], Ks_lo + boff);
                MMA_BF16(S[2 * pr],     ahi, bh[0], bh[1]);
                MMA_BF16(S[2 * pr],     ahi, bl[0], bl[1]);
                MMA_BF16(S[2 * pr],     alo, bh[0], bh[1]);
                MMA_BF16(S[2 * pr + 1], ahi, bh[2], bh[3]);
                MMA_BF16(S[2 * pr + 1], ahi, bl[2], bl[3]);
                MMA_BF16(S[2 * pr + 1], alo, bh[2], bh[3]);
            }
        }

        if (kb >= 2 * qb) {
#pragma unroll
            for (int t = 0; t < 4; t++) {
                int colb = kb * 32 + t * 8 + 2 * tg;
#pragma unroll
                for (int e = 0; e < 4; e++) {
                    int col = colb + (e & 1);
                    int row = q0 + wid * 16 + gp + ((e >= 2) ? 8 : 0);
                    S[t][e] = (col <= row) ? S[t][e] * scale : -1e30f;
                }
            }
        } else {
#pragma unroll
            for (int t = 0; t < 4; t++)
#pragma unroll
                for (int e = 0; e < 4; e++) S[t][e] *= scale;
        }

#pragma unroll
        for (int h = 0; h < 2; h++) {
            float mx = -1e30f;
#pragma unroll
            for (int t = 0; t < 4; t++)
                mx = fmaxf(mx, fmaxf(S[t][2 * h], S[t][2 * h + 1]));
            mx = fmaxf(mx, __shfl_xor_sync(0xffffffffu, mx, 1));
            mx = fmaxf(mx, __shfl_xor_sync(0xffffffffu, mx, 2));
            float m_new = fmaxf(m_i[h], mx);
            float alpha = __expf(m_i[h] - m_new);
            float sum = 0.0f;
#pragma unroll
            for (int t = 0; t < 4; t++) {
                S[t][2 * h]     = __expf(S[t][2 * h] - m_new);
                S[t][2 * h + 1] = __expf(S[t][2 * h + 1] - m_new);
                sum += S[t][2 * h] + S[t][2 * h + 1];
            }
            sum += __shfl_xor_sync(0xffffffffu, sum, 1);
            sum += __shfl_xor_sync(0xffffffffu, sum, 2);
            l_i[h] = l_i[h] * alpha + sum;
            m_i[h] = m_new;
#pragma unroll
            for (int nt = 0; nt < 16; nt++) {
                O[nt][2 * h] *= alpha;
                O[nt][2 * h + 1] *= alpha;
            }
        }

#pragma unroll
        for (int kt2 = 0; kt2 < 2; kt2++) {
            uint32_t phi[4], plo[4];
            {
                float* p0 = S[2 * kt2];
                float* p1 = S[2 * kt2 + 1];
                float h00 = __bfloat162float(__float2bfloat16_rn(p0[0]));
                float h01 = __bfloat162float(__float2bfloat16_rn(p0[1]));
                float h02 = __bfloat162float(__float2bfloat16_rn(p0[2]));
                float h03 = __bfloat162float(__float2bfloat16_rn(p0[3]));
                float h10 = __bfloat162float(__float2bfloat16_rn(p1[0]));
                float h11 = __bfloat162float(__float2bfloat16_rn(p1[1]));
                float h12 = __bfloat162float(__float2bfloat16_rn(p1[2]));
                float h13 = __bfloat162float(__float2bfloat16_rn(p1[3]));
                phi[0] = pack_bf16(h00, h01);
                phi[1] = pack_bf16(h02, h03);
                phi[2] = pack_bf16(h10, h11);
                phi[3] = pack_bf16(h12, h13);
                plo[0] = pack_bf16(p0[0] - h00, p0[1] - h01);
                plo[1] = pack_bf16(p0[2] - h02, p0[3] - h03);
                plo[2] = pack_bf16(p1[0] - h10, p1[1] - h11);
                plo[3] = pack_bf16(p1[2] - h12, p1[3] - h13);
            }
#pragma unroll
            for (int dp = 0; dp < 8; dp++) {
                uint32_t voff = (uint32_t)((kt2 * 16 + ((lane >> 3) & 1) * 8 + (lane & 7)) * APB_
                                           + (dp * 16 + (lane >> 4) * 8) * 2);
                uint32_t bh[4], bl[4];
                LDSM_X4_T(bh[0], bh[1], bh[2], bh[3], Vs_hi + voff);
                LDSM_X4_T(bl[0], bl[1], bl[2], bl[3], Vs_lo + voff);
                MMA_BF16(O[2 * dp],     phi, bh[0], bh[1]);
                MMA_BF16(O[2 * dp],     phi, bl[0], bl[1]);
                MMA_BF16(O[2 * dp],     plo, bh[0], bh[1]);
                MMA_BF16(O[2 * dp + 1], phi, bh[2], bh[3]);
                MMA_BF16(O[2 * dp + 1], phi, bl[2], bl[3]);
                MMA_BF16(O[2 * dp + 1], plo, bh[2], bh[3]);
            }
        }
        __syncthreads();
    }

    // ---- finalize + write bf16 hi/lo split directly
#pragma unroll
    for (int h = 0; h < 2; h++) {
        float inv = 1.0f / l_i[h];
        int row = q0 + wid * 16 + gp + h * 8;
        size_t base = (size_t)row * H_ + head * HD_;
#pragma unroll
        for (int nt = 0; nt < 16; nt++) {
            float o0 = O[nt][2 * h] * inv;
            float o1 = O[nt][2 * h + 1] * inv;
            float hh0 = __bfloat162float(__float2bfloat16_rn(o0));
            float hh1 = __bfloat162float(__float2bfloat16_rn(o1));
            size_t off = base + nt * 8 + 2 * tg;
            *(uint32_t*)(out_hi + off) = pack_bf16(hh0, hh1);
            *(uint32_t*)(out_lo + off) = pack_bf16(o0 - hh0, o1 - hh1);
        }
    }
}

// ---------------------------------------------------------------------------
extern "C" void kernel_launch(void* const* d_in, const int* in_sizes, int n_in,
                              void* d_out, int out_size)
{
    const float* hidden = (const float*)d_in[0];   // [1,2048,4096]
    const float* Wqkv   = (const float*)d_in[1];   // [6144,4096]
    const float* Wo     = (const float*)d_in[2];   // [4096,4096]
    float* out = (float*)d_out;                    // [1,2048,4096]

    float* qkv_ptr = nullptr;
    __nv_bfloat16 *hid_hi, *hid_lo, *wqkv_hi, *wqkv_lo, *wo_hi, *wo_lo, *attn_hi, *attn_lo;
    __nv_bfloat16 *q_hi, *q_lo, *k_hi, *k_lo, *v_hi, *v_lo;
    cudaGetSymbolAddress((void**)&qkv_ptr, g_qkv);
    cudaGetSymbolAddress((void**)&hid_hi, g_hid_hi);
    cudaGetSymbolAddress((void**)&hid_lo, g_hid_lo);
    cudaGetSymbolAddress((void**)&wqkv_hi, g_wqkv_hi);
    cudaGetSymbolAddress((void**)&wqkv_lo, g_wqkv_lo);
    cudaGetSymbolAddress((void**)&wo_hi, g_wo_hi);
    cudaGetSymbolAddress((void**)&wo_lo, g_wo_lo);
    cudaGetSymbolAddress((void**)&attn_hi, g_attn_hi);
    cudaGetSymbolAddress((void**)&attn_lo, g_attn_lo);
    cudaGetSymbolAddress((void**)&q_hi, g_q_hi);
    cudaGetSymbolAddress((void**)&q_lo, g_q_lo);
    cudaGetSymbolAddress((void**)&k_hi, g_k_hi);
    cudaGetSymbolAddress((void**)&k_lo, g_k_lo);
    cudaGetSymbolAddress((void**)&v_hi, g_v_hi);
    cudaGetSymbolAddress((void**)&v_lo, g_v_lo);

    cudaFuncSetAttribute(gemm_mma_kernel,
                         cudaFuncAttributeMaxDynamicSharedMemorySize, GEMM_SMEM_BYTES);
    cudaFuncSetAttribute(flash_attn_mma_kernel,
                         cudaFuncAttributeMaxDynamicSharedMemorySize, ATTN_SMEM_BYTES);

    // 0) split-convert inputs
    {
        int n4;
        n4 = (S_ * H_) / 4;
        cvt_split_kernel<<<(n4 + 255) / 256, 256>>>(hidden, hid_hi, hid_lo, n4);
        n4 = (QKV_O * H_) / 4;
        cvt_split_kernel<<<(n4 + 255) / 256, 256>>>(Wqkv, wqkv_hi, wqkv_lo, n4);
        n4 = (H_ * H_) / 4;
        cvt_split_kernel<<<(n4 + 255) / 256, 256>>>(Wo, wo_hi, wo_lo, n4);
    }

    // 1) QKV projection (HMMA bf16x3), m-fastest 1-D grid
    {
        int mt = S_ / 128, nt = QKV_O / 128;
        gemm_mma_kernel<<<mt * nt, 256, GEMM_SMEM_BYTES>>>(
            hid_hi, hid_lo, wqkv_hi, wqkv_lo, qkv_ptr, QKV_O, H_, mt);
    }

    // 2) RoPE + split-convert Q,K; split-convert V
    {
        rope_cvt_kernel<<<S_, 256>>>(qkv_ptr, q_hi, q_lo, k_hi, k_lo);
        int n4 = (S_ * NKV_ * HD_) / 4;
        v_cvt_kernel<<<(n4 + 255) / 256, 256>>>(qkv_ptr, v_hi, v_lo);
    }

    // 3) Flash attention (HMMA bf16x3), writes hi/lo split directly
    {
        dim3 grid(S_ / 64, NH_);
        flash_attn_mma_kernel<<<grid, 128, ATTN_SMEM_BYTES>>>(
            q_hi, q_lo, k_hi, k_lo, v_hi, v_lo, attn_hi, attn_lo);
    }

    // 4) Output projection (HMMA bf16x3), m-fastest 1-D grid
    {
        int mt = S_ / 128, nt = H_ / 128;
        gemm_mma_kernel<<<mt * nt, 256, GEMM_SMEM_BYTES>>>(
            attn_hi, attn_lo, wo_hi, wo_lo, out, H_, H_, mt);
    }
}